// round 9
// baseline (speedup 1.0000x reference)
#include <cuda_runtime.h>
#include <cstdint>

// GIN_38216619000492: GINConv (eps=0) + 2-layer MLP.
//   h = x + segment_sum(x[src], dst);  hid = relu(h@W1+b1);  out = hid@W2+b2
// N=50000, E=800000, edge_index int32. MLP via mma.sync tf32 (base sm_100).
// R9: fragment-PACKED smem layouts -> every mma operand load is one LDS.128.
// Packed fragment = [tile][kstep(s)][lane 0..31][4 words] where lane=(g<<2)|tg:
//   A quad: (row g,k=8ks+tg) (row g+8, same k) (row g, k+4) (row g+8, k+4)
//   B quad: (b0 @ks even)(b1 @ks even)(b0 @ks odd)(b1 @ks odd), b0=B[8t+g][8ks+tg], b1=+4

#define D_IN  64
#define D_H   256
#define D_OUT 64
#define NMAX  50000

static __device__ float g_h[(size_t)NMAX * D_IN];
static __device__ float g_B1[16384];   // packed W1^T frags: [32 ntl][4 ks2][128]
static __device__ float g_B2[16384];   // packed W2^T frags: [8 ntl][16 ks2][128]

__device__ __forceinline__ uint32_t f2tf32(float f) {
    uint32_t u;
    asm("cvt.rna.tf32.f32 %0, %1;" : "=r"(u) : "f"(f));
    return u;
}

__device__ __forceinline__ void mma8(float* c, uint32_t a0, uint32_t a1,
                                     uint32_t a2, uint32_t a3,
                                     uint32_t b0, uint32_t b1) {
    asm volatile(
        "mma.sync.aligned.m16n8k8.row.col.f32.tf32.tf32.f32 "
        "{%0,%1,%2,%3}, {%4,%5,%6,%7}, {%8,%9}, {%0,%1,%2,%3};"
        : "+f"(c[0]), "+f"(c[1]), "+f"(c[2]), "+f"(c[3])
        : "r"(a0), "r"(a1), "r"(a2), "r"(a3), "r"(b0), "r"(b1));
}

// ---------------------------------------------------------------------------
// Kernel 1: zero g_h (scatter adds agg; MLP adds x during staging).
// ---------------------------------------------------------------------------
__global__ void gin_zero(int n4) {
    int i = blockIdx.x * blockDim.x + threadIdx.x;
    if (i < n4) ((float4*)g_h)[i] = make_float4(0.f, 0.f, 0.f, 0.f);
}

// ---------------------------------------------------------------------------
// Kernel 1b: build PACKED tf32 weight fragment images.
// ---------------------------------------------------------------------------
__global__ void gin_prep(const float* __restrict__ W1, const float* __restrict__ W2) {
    int i = blockIdx.x * blockDim.x + threadIdx.x;
    if (i >= 32768) return;
    if (i < 16384) {                       // W1[k][n], k<64, n<256
        int k = i >> 8, n = i & 255;
        int ntl = n >> 3, g = n & 7;
        int ks = k >> 3, kin = k & 7, tg = kin & 3, half = kin >> 2;
        int ks2 = ks >> 1, kp = ks & 1;
        int addr = (ntl * 4 + ks2) * 128 + (g * 4 + tg) * 4 + kp * 2 + half;
        ((uint32_t*)g_B1)[addr] = f2tf32(W1[i]);
    } else {                               // W2[k][n], k<256, n<64
        int j = i - 16384;
        int k = j >> 6, n = j & 63;
        int ntl = n >> 3, g = n & 7;
        int ks = k >> 3, kin = k & 7, tg = kin & 3, half = kin >> 2;
        int ks2 = ks >> 1, kp = ks & 1;
        int addr = (ntl * 16 + ks2) * 128 + (g * 4 + tg) * 4 + kp * 2 + half;
        ((uint32_t*)g_B2)[addr] = f2tf32(W2[j]);
    }
}

// ---------------------------------------------------------------------------
// Kernel 2: scatter-add, red.global.add.v4.f32, 16 threads/edge (proven).
// ---------------------------------------------------------------------------
__global__ void gin_scatter(const float* __restrict__ x,
                            const int* __restrict__ ei, int E) {
    int w = blockIdx.x * blockDim.x + threadIdx.x;
    int e = w >> 4;
    if (e >= E) return;
    int c = (w & 15) << 2;
    int src = ei[e];
    int dst = ei[E + e];
    float4 v = *(const float4*)(x + (size_t)src * D_IN + c);
    float* o = g_h + (size_t)dst * D_IN + c;
    asm volatile("red.global.add.v4.f32 [%0], {%1, %2, %3, %4};"
                 :: "l"(o), "f"(v.x), "f"(v.y), "f"(v.z), "f"(v.w)
                 : "memory");
}

// ---------------------------------------------------------------------------
// Kernel 3: fused MLP, tf32 mma.sync, packed fragments. 128 rows/CTA, 16 warps.
// Warp w: mw=w&7 (rows 16mw..16mw+16), nh=w>>3 (n-half).
// SMEM word map (aliased):
//   phase1: apack1 @0      [8 rblk][8 ks][128]      =  8192 w
//           bpack1 @8192   [32 ntl][4 ks2][128]     = 16384 w
//   phase2: apack2 rblk<6  @0 (overlays phase1)     = 24576 w
//           apack2 rblk>=6 @APK2X                   =  8192 w
//   bpack2 @24576 [8 ntl][16 ks2][128]              = 16384 w  (disjoint)
//   APK2X @40960; b1s @49152 [256]; b2s @49408 [64]; total 49472 w = 197888 B.
// ---------------------------------------------------------------------------
#define APK1_F   0
#define BPK1_F   8192
#define BPK2_F   24576
#define APK2X_F  40960
#define B1S_F    49152
#define B2S_F    49408
#define SMEM_BYTES (49472 * 4)

__device__ __forceinline__ int apack2_base(int rblk) {   // word offset of [rblk][ks=0]
    return (rblk < 6) ? rblk * 4096 : (APK2X_F + (rblk - 6) * 4096);
}

__global__ __launch_bounds__(512, 1)
void gin_mlp(const float* __restrict__ x,
             const float* __restrict__ b1, const float* __restrict__ b2,
             float* __restrict__ out, int N) {
    extern __shared__ float s[];
    uint32_t* su = (uint32_t*)s;

    const int t = threadIdx.x;
    const int w = t >> 5;
    const int mw = w & 7;
    const int nh = w >> 3;
    const int lane = t & 31;
    const int g = lane >> 2;
    const int tg = lane & 3;
    const int row0 = blockIdx.x * 128;

    // ---- Stage packed B1, B2, biases (linear float4 memcpy) ----
    {
        const float4* g1 = (const float4*)g_B1;
        const float4* g2 = (const float4*)g_B2;
        float4* s1 = (float4*)(s + BPK1_F);
        float4* s2 = (float4*)(s + BPK2_F);
        #pragma unroll 4
        for (int i = t; i < 4096; i += 512) s1[i] = g1[i];
        #pragma unroll 4
        for (int i = t; i < 4096; i += 512) s2[i] = g2[i];
        if (t < 64) ((float4*)(s + B1S_F))[t] = ((const float4*)b1)[t];
        if (t < 16) ((float4*)(s + B2S_F))[t] = ((const float4*)b2)[t];
    }

    // ---- Stage apack1 = packed tf32(x + g_h) fragments ----
    #pragma unroll 4
    for (int i = t; i < 2048; i += 512) {          // 128 rows x 16 float4
        int r = i >> 4, k4 = (i & 15) << 2;
        float4 v = make_float4(0.f, 0.f, 0.f, 0.f);
        int gr = row0 + r;
        if (gr < N) {
            float4 xv = *(const float4*)(x   + (size_t)gr * D_IN + k4);
            float4 hv = *(const float4*)(g_h + (size_t)gr * D_IN + k4);
            v = make_float4(xv.x + hv.x, xv.y + hv.y, xv.z + hv.z, xv.w + hv.w);
        }
        int rblk = r >> 4, rb = r & 15;
        int gr8 = rb & 7, wrow = rb >> 3;
        int ks = k4 >> 3, half = (k4 & 7) >> 2;
        int base = APK1_F + (rblk * 8 + ks) * 128 + gr8 * 16 + half * 2 + wrow;
        su[base + 0]  = f2tf32(v.x);
        su[base + 4]  = f2tf32(v.y);
        su[base + 8]  = f2tf32(v.z);
        su[base + 12] = f2tf32(v.w);
    }
    __syncthreads();

    // ---- GEMM1: rows [16mw,16mw+16) x cols [nh*128, nh*128+128) ----
    float acc[16][4];
    #pragma unroll
    for (int nt = 0; nt < 16; nt++)
        #pragma unroll
        for (int j = 0; j < 4; j++) acc[nt][j] = 0.f;

    {
        const uint32_t* A1 = su + APK1_F + mw * 8 * 128 + lane * 4;
        const uint32_t* B1p = su + BPK1_F + (nh * 16) * 512 + lane * 4;
        #pragma unroll
        for (int ks2 = 0; ks2 < 4; ks2++) {
            uint4 aE = *(const uint4*)(A1 + (2 * ks2) * 128);
            uint4 aO = *(const uint4*)(A1 + (2 * ks2 + 1) * 128);
            #pragma unroll
            for (int c4 = 0; c4 < 4; c4++) {
                uint4 bv[4];
                #pragma unroll
                for (int q = 0; q < 4; q++)
                    bv[q] = *(const uint4*)(B1p + (c4 * 4 + q) * 512 + ks2 * 128);
                #pragma unroll
                for (int q = 0; q < 4; q++) {
                    mma8(acc[c4 * 4 + q], aE.x, aE.y, aE.z, aE.w, bv[q].x, bv[q].y);
                    mma8(acc[c4 * 4 + q], aO.x, aO.y, aO.z, aO.w, bv[q].z, bv[q].w);
                }
            }
        }
    }
    __syncthreads();   // phase1 reads done; apack2 may overlay apack1/bpack1

    // ---- Epilogue 1: write packed tf32(relu(D1+b1)) fragments (apack2) ----
    {
        const int tb = (tg < 2) ? 2 * tg : 2 * tg - 4;   // target tg in quad
        const int wb = (tg < 2) ? 0 : 2;                 // half*2
        const int ab = apack2_base(mw) + g * 16;
        #pragma unroll
        for (int ntl = 0; ntl < 16; ntl++) {
            int ks = nh * 16 + ntl;                      // absolute col block
            int c0 = ks * 8 + 2 * tg;
            float bb0 = s[B1S_F + c0], bb1 = s[B1S_F + c0 + 1];
            int base = ab + ks * 128;
            su[base + tb * 4 + wb]           = f2tf32(fmaxf(acc[ntl][0] + bb0, 0.f));
            su[base + (tb + 1) * 4 + wb]     = f2tf32(fmaxf(acc[ntl][1] + bb1, 0.f));
            su[base + tb * 4 + wb + 1]       = f2tf32(fmaxf(acc[ntl][2] + bb0, 0.f));
            su[base + (tb + 1) * 4 + wb + 1] = f2tf32(fmaxf(acc[ntl][3] + bb1, 0.f));
        }
    }
    __syncthreads();

    // ---- GEMM2: rows [16mw,16mw+16) x cols [nh*32, nh*32+32) ----
    float acc2[4][4];
    #pragma unroll
    for (int nt = 0; nt < 4; nt++)
        #pragma unroll
        for (int j = 0; j < 4; j++) acc2[nt][j] = 0.f;

    {
        const uint32_t* A2 = su + apack2_base(mw) + lane * 4;
        const uint32_t* B2p = su + BPK2_F + (nh * 4) * 2048 + lane * 4;
        #pragma unroll 4
        for (int ks2 = 0; ks2 < 16; ks2++) {
            uint4 aE = *(const uint4*)(A2 + (2 * ks2) * 128);
            uint4 aO = *(const uint4*)(A2 + (2 * ks2 + 1) * 128);
            uint4 bv[4];
            #pragma unroll
            for (int q = 0; q < 4; q++)
                bv[q] = *(const uint4*)(B2p + q * 2048 + ks2 * 128);
            #pragma unroll
            for (int q = 0; q < 4; q++) {
                mma8(acc2[q], aE.x, aE.y, aE.z, aE.w, bv[q].x, bv[q].y);
                mma8(acc2[q], aO.x, aO.y, aO.z, aO.w, bv[q].z, bv[q].w);
            }
        }
    }

    // ---- Epilogue 2: out = D2 + b2 (fp32) ----
    {
        int gr_lo = row0 + 16 * mw + g;
        int gr_hi = gr_lo + 8;
        #pragma unroll
        for (int ntl = 0; ntl < 4; ntl++) {
            int col = (nh * 4 + ntl) * 8 + 2 * tg;
            float bb0 = s[B2S_F + col], bb1 = s[B2S_F + col + 1];
            if (gr_lo < N) {
                float2 v = make_float2(acc2[ntl][0] + bb0, acc2[ntl][1] + bb1);
                *(float2*)(out + (size_t)gr_lo * D_OUT + col) = v;
            }
            if (gr_hi < N) {
                float2 v = make_float2(acc2[ntl][2] + bb0, acc2[ntl][3] + bb1);
                *(float2*)(out + (size_t)gr_hi * D_OUT + col) = v;
            }
        }
    }
}

// ---------------------------------------------------------------------------
// Launch. Inputs: x[f32], edge_index[i32 2xE], W1, b1, W2, b2.
// ---------------------------------------------------------------------------
extern "C" void kernel_launch(void* const* d_in, const int* in_sizes, int n_in,
                              void* d_out, int out_size) {
    const float* x  = (const float*)d_in[0];
    const int*   ei = (const int*)d_in[1];
    const float* W1 = (const float*)d_in[2];
    const float* b1 = (const float*)d_in[3];
    const float* W2 = (const float*)d_in[4];
    const float* b2 = (const float*)d_in[5];
    float* out = (float*)d_out;

    const int N = in_sizes[0] / D_IN;   // 50000
    const int E = in_sizes[1] / 2;      // 800000

    cudaFuncSetAttribute(gin_mlp, cudaFuncAttributeMaxDynamicSharedMemorySize,
                         SMEM_BYTES);

    int n4 = N * (D_IN / 4);
    gin_zero<<<(n4 + 255) / 256, 256>>>(n4);
    gin_prep<<<128, 256>>>(W1, W2);

    int work = E * 16;
    gin_scatter<<<(work + 255) / 256, 256>>>(x, ei, E);

    gin_mlp<<<(N + 127) / 128, 512, SMEM_BYTES>>>(x, b1, b2, out, N);
}

// round 10
// speedup vs baseline: 1.0206x; 1.0206x over previous
#include <cuda_runtime.h>
#include <cstdint>

// GIN_38216619000492: GINConv (eps=0) + 2-layer MLP.
//   h = x + segment_sum(x[src], dst);  hid = relu(h@W1+b1);  out = hid@W2+b2
// N=50000, E=800000, edge_index int32. MLP via mma.sync tf32 (base sm_100).
// R10: R8's scalar-LDS kernel (crossbar bytes = the resource; LDS.128 was
// neutral-negative) with GEMM1 repartitioned P_m=4 x P_n=4 (B-replication
// halved, 2x per-warp ILP) + R9's zero-fill + fused "+x" staging.

#define D_IN  64
#define D_H   256
#define D_OUT 64
#define NMAX  50000

static __device__ float g_h[(size_t)NMAX * D_IN];
static __device__ float g_B1[17408];   // W1^T tf32 image: [n=256][k=64], stride 68
static __device__ float g_B2[16640];   // W2^T tf32 image: [n=64][k=256], stride 260

__device__ __forceinline__ uint32_t f2tf32(float f) {
    uint32_t u;
    asm("cvt.rna.tf32.f32 %0, %1;" : "=r"(u) : "f"(f));
    return u;
}

__device__ __forceinline__ void mma8(float* c, uint32_t a0, uint32_t a1,
                                     uint32_t a2, uint32_t a3,
                                     uint32_t b0, uint32_t b1) {
    asm volatile(
        "mma.sync.aligned.m16n8k8.row.col.f32.tf32.tf32.f32 "
        "{%0,%1,%2,%3}, {%4,%5,%6,%7}, {%8,%9}, {%0,%1,%2,%3};"
        : "+f"(c[0]), "+f"(c[1]), "+f"(c[2]), "+f"(c[3])
        : "r"(a0), "r"(a1), "r"(a2), "r"(a3), "r"(b0), "r"(b1));
}

// ---------------------------------------------------------------------------
// Kernel 1: zero g_h (scatter adds agg; MLP staging adds x).
// ---------------------------------------------------------------------------
__global__ void gin_zero(int n4) {
    int i = blockIdx.x * blockDim.x + threadIdx.x;
    if (i < n4) ((float4*)g_h)[i] = make_float4(0.f, 0.f, 0.f, 0.f);
}

// ---------------------------------------------------------------------------
// Kernel 1b: transpose + tf32-convert weights into strided global images.
//   g_B1[n*68+k]  = tf32(W1[k][n]);  g_B2[n*260+k] = tf32(W2[k][n])
// Strides ≡4 (mod 32) floats -> conflict-free fragment LDS.
// ---------------------------------------------------------------------------
__global__ void gin_prep(const float* __restrict__ W1, const float* __restrict__ W2) {
    int i = blockIdx.x * blockDim.x + threadIdx.x;
    if (i >= 32768) return;
    if (i < 16384) {
        int k = i >> 8, n = i & 255;
        ((uint32_t*)g_B1)[n * 68 + k] = f2tf32(W1[i]);
    } else {
        int j = i - 16384;
        int k = j >> 6, n = j & 63;
        ((uint32_t*)g_B2)[n * 260 + k] = f2tf32(W2[j]);
    }
}

// ---------------------------------------------------------------------------
// Kernel 2: scatter-add, red.global.add.v4.f32, 16 threads/edge (proven;
// at the LTS byte cap -> not worth touching).
// ---------------------------------------------------------------------------
__global__ void gin_scatter(const float* __restrict__ x,
                            const int* __restrict__ ei, int E) {
    int w = blockIdx.x * blockDim.x + threadIdx.x;
    int e = w >> 4;
    if (e >= E) return;
    int c = (w & 15) << 2;
    int src = ei[e];
    int dst = ei[E + e];
    float4 v = *(const float4*)(x + (size_t)src * D_IN + c);
    float* o = g_h + (size_t)dst * D_IN + c;
    asm volatile("red.global.add.v4.f32 [%0], {%1, %2, %3, %4};"
                 :: "l"(o), "f"(v.x), "f"(v.y), "f"(v.z), "f"(v.w)
                 : "memory");
}

// ---------------------------------------------------------------------------
// Kernel 3: fused MLP, tf32 mma.sync. 128 rows/CTA, 16 warps (512 thr).
// GEMM1 partition (NEW): warp w -> mq=w&3 (rows [32mq,32mq+32)),
//                                  nq=w>>2 (cols [64nq,64nq+64)); 64 accs.
// GEMM2 partition (R8):  warp w -> mw=w&7 (rows [16mw,16mw+16)),
//                                  nh=w>>3 (cols [32nh,32nh+32)); 16 accs.
// SMEM layout identical to R7/R8 (205,568 B, validated):
//   phase1: hs @0 [128][68], B1 @8704 [256][68]
//   phase2: hid rows 0..95 @0 (stride 260), rows 96..127 @42752
//   B2 @26112 [64][260]; b1s @51072; b2s @51328.
// ---------------------------------------------------------------------------
#define HS_F    0
#define B1_F    8704
#define HID0_F  0
#define B2_F    26112
#define HID1_F  42752
#define B1S_F   51072
#define B2S_F   51328
#define SMEM_BYTES (51392 * 4)

__device__ __forceinline__ int hid_off(int r) {
    return (r < 96) ? (HID0_F + r * 260) : (HID1_F + (r - 96) * 260);
}

__global__ __launch_bounds__(512, 1)
void gin_mlp(const float* __restrict__ x,
             const float* __restrict__ b1, const float* __restrict__ b2,
             float* __restrict__ out, int N) {
    extern __shared__ float s[];
    uint32_t* su = (uint32_t*)s;

    const int t = threadIdx.x;
    const int w = t >> 5;
    const int lane = t & 31;
    const int g = lane >> 2;      // group id (0..7)
    const int tg = lane & 3;      // thread-in-group (0..3)
    const int row0 = blockIdx.x * 128;

    // ---- Stage B1, B2, biases ----
    {
        const float4* g1 = (const float4*)g_B1;
        const float4* g2 = (const float4*)g_B2;
        float4* s1 = (float4*)(s + B1_F);
        float4* s2 = (float4*)(s + B2_F);
        #pragma unroll 4
        for (int i = t; i < 4352; i += 512) s1[i] = g1[i];
        #pragma unroll 4
        for (int i = t; i < 4160; i += 512) s2[i] = g2[i];
        if (t < 64) ((float4*)(s + B1S_F))[t] = ((const float4*)b1)[t];
        if (t < 16) ((float4*)(s + B2S_F))[t] = ((const float4*)b2)[t];
    }

    // ---- Stage A1 = tf32(x + g_h) [128][68] ----
    #pragma unroll 4
    for (int i = t; i < 2048; i += 512) {          // 128 rows x 16 float4
        int r = i >> 4, k4 = (i & 15) << 2;
        float4 v = make_float4(0.f, 0.f, 0.f, 0.f);
        int gr = row0 + r;
        if (gr < N) {
            float4 xv = *(const float4*)(x   + (size_t)gr * D_IN + k4);
            float4 hv = *(const float4*)(g_h + (size_t)gr * D_IN + k4);
            v = make_float4(xv.x + hv.x, xv.y + hv.y, xv.z + hv.z, xv.w + hv.w);
        }
        uint4 u = make_uint4(f2tf32(v.x), f2tf32(v.y), f2tf32(v.z), f2tf32(v.w));
        *(uint4*)(s + HS_F + r * 68 + k4) = u;
    }
    __syncthreads();

    // ---- GEMM1: warp = rows [32mq,32mq+32) x cols [64nq,64nq+64) ----
    const int mq = w & 3;
    const int nq = w >> 2;
    float acc[2][8][4];
    #pragma unroll
    for (int b = 0; b < 2; b++)
        #pragma unroll
        for (int nt = 0; nt < 8; nt++)
            #pragma unroll
            for (int j = 0; j < 4; j++) acc[b][nt][j] = 0.f;

    {
        const uint32_t* alo0 = su + HS_F + (32 * mq + g) * 68;
        const uint32_t* ahi0 = alo0 + 8 * 68;
        const uint32_t* alo1 = alo0 + 16 * 68;
        const uint32_t* ahi1 = alo0 + 24 * 68;
        const uint32_t* Bb = su + B1_F + (nq * 64 + g) * 68;   // n = nq*64 + ntl*8 + g
        #pragma unroll
        for (int ks = 0; ks < 8; ks++) {
            int kb = ks * 8;
            uint32_t a0[2], a1[2], a2[2], a3[2];
            a0[0] = alo0[kb + tg];     a1[0] = ahi0[kb + tg];
            a2[0] = alo0[kb + tg + 4]; a3[0] = ahi0[kb + tg + 4];
            a0[1] = alo1[kb + tg];     a1[1] = ahi1[kb + tg];
            a2[1] = alo1[kb + tg + 4]; a3[1] = ahi1[kb + tg + 4];
            #pragma unroll
            for (int c4 = 0; c4 < 2; c4++) {
                uint32_t bv[4][2];
                #pragma unroll
                for (int q = 0; q < 4; q++) {
                    int ntl = c4 * 4 + q;
                    bv[q][0] = Bb[ntl * 8 * 68 + kb + tg];
                    bv[q][1] = Bb[ntl * 8 * 68 + kb + tg + 4];
                }
                #pragma unroll
                for (int q = 0; q < 4; q++) {
                    mma8(acc[0][c4 * 4 + q], a0[0], a1[0], a2[0], a3[0], bv[q][0], bv[q][1]);
                    mma8(acc[1][c4 * 4 + q], a0[1], a1[1], a2[1], a3[1], bv[q][0], bv[q][1]);
                }
            }
        }
    }
    __syncthreads();   // all reads of hs/B1 done; hid may alias them

    // ---- Epilogue 1: hid = tf32(relu(D1 + b1)) ----
    {
        #pragma unroll
        for (int b = 0; b < 2; b++) {
            int r_lo = 32 * mq + 16 * b + g;
            float* h_lo = s + hid_off(r_lo);
            float* h_hi = s + hid_off(r_lo + 8);
            #pragma unroll
            for (int ntl = 0; ntl < 8; ntl++) {
                int col = (nq * 8 + ntl) * 8 + 2 * tg;
                float bb0 = s[B1S_F + col], bb1 = s[B1S_F + col + 1];
                uint2 u0, u1;
                u0.x = f2tf32(fmaxf(acc[b][ntl][0] + bb0, 0.f));
                u0.y = f2tf32(fmaxf(acc[b][ntl][1] + bb1, 0.f));
                u1.x = f2tf32(fmaxf(acc[b][ntl][2] + bb0, 0.f));
                u1.y = f2tf32(fmaxf(acc[b][ntl][3] + bb1, 0.f));
                *(uint2*)(h_lo + col) = u0;
                *(uint2*)(h_hi + col) = u1;
            }
        }
    }
    __syncthreads();

    // ---- GEMM2: warp = rows [16mw,16mw+16) x cols [32nh,32nh+32) (R8) ----
    const int mw = w & 7;
    const int nh = w >> 3;
    float acc2[4][4];
    #pragma unroll
    for (int nt = 0; nt < 4; nt++)
        #pragma unroll
        for (int j = 0; j < 4; j++) acc2[nt][j] = 0.f;

    {
        const uint32_t* arow_lo = su + hid_off(16 * mw + g);
        const uint32_t* arow_hi = su + hid_off(16 * mw + g + 8);
        const uint32_t* Bb = su + B2_F + (nh * 32 + g) * 260;   // n = nh*32 + ntl*8 + g
        #pragma unroll 4
        for (int ks = 0; ks < 32; ks++) {
            int kb = ks * 8;
            uint32_t a0 = arow_lo[kb + tg];
            uint32_t a1 = arow_hi[kb + tg];
            uint32_t a2 = arow_lo[kb + tg + 4];
            uint32_t a3 = arow_hi[kb + tg + 4];
            uint32_t bv[4][2];
            #pragma unroll
            for (int q = 0; q < 4; q++) {
                bv[q][0] = Bb[q * 8 * 260 + kb + tg];
                bv[q][1] = Bb[q * 8 * 260 + kb + tg + 4];
            }
            #pragma unroll
            for (int q = 0; q < 4; q++)
                mma8(acc2[q], a0, a1, a2, a3, bv[q][0], bv[q][1]);
        }
    }

    // ---- Epilogue 2: out = D2 + b2 (fp32) ----
    {
        int gr_lo = row0 + 16 * mw + g;
        int gr_hi = gr_lo + 8;
        #pragma unroll
        for (int ntl = 0; ntl < 4; ntl++) {
            int col = (nh * 4 + ntl) * 8 + 2 * tg;
            float bb0 = s[B2S_F + col], bb1 = s[B2S_F + col + 1];
            if (gr_lo < N) {
                float2 v = make_float2(acc2[ntl][0] + bb0, acc2[ntl][1] + bb1);
                *(float2*)(out + (size_t)gr_lo * D_OUT + col) = v;
            }
            if (gr_hi < N) {
                float2 v = make_float2(acc2[ntl][2] + bb0, acc2[ntl][3] + bb1);
                *(float2*)(out + (size_t)gr_hi * D_OUT + col) = v;
            }
        }
    }
}

// ---------------------------------------------------------------------------
// Launch. Inputs: x[f32], edge_index[i32 2xE], W1, b1, W2, b2.
// ---------------------------------------------------------------------------
extern "C" void kernel_launch(void* const* d_in, const int* in_sizes, int n_in,
                              void* d_out, int out_size) {
    const float* x  = (const float*)d_in[0];
    const int*   ei = (const int*)d_in[1];
    const float* W1 = (const float*)d_in[2];
    const float* b1 = (const float*)d_in[3];
    const float* W2 = (const float*)d_in[4];
    const float* b2 = (const float*)d_in[5];
    float* out = (float*)d_out;

    const int N = in_sizes[0] / D_IN;   // 50000
    const int E = in_sizes[1] / 2;      // 800000

    cudaFuncSetAttribute(gin_mlp, cudaFuncAttributeMaxDynamicSharedMemorySize,
                         SMEM_BYTES);

    int n4 = N * (D_IN / 4);
    gin_zero<<<(n4 + 255) / 256, 256>>>(n4);
    gin_prep<<<128, 256>>>(W1, W2);

    int work = E * 16;
    gin_scatter<<<(work + 255) / 256, 256>>>(x, ei, E);

    gin_mlp<<<(N + 127) / 128, 512, SMEM_BYTES>>>(x, b1, b2, out, N);
}